// round 6
// baseline (speedup 1.0000x reference)
#include <cuda_runtime.h>
#include <math.h>
#include <stdint.h>

// Problem dims (fixed)
#define BB   16
#define LL   2048
#define HH   256
#define NN   64
#define NLAY 4
#define IND  40
#define OUTD 33

// Chunked-scan config
#define CH    4
#define CLEN  512   // LL / CH

typedef unsigned long long ull;

// ------------------------------------------------------------------
// Scratch (device globals)
// ------------------------------------------------------------------
__device__ float g_h[BB * LL * HH];   // residual stream, [m][h]
__device__ float g_zt[BB * HH * LL];  // layernorm output, TRANSPOSED [seq][l]
__device__ float g_yt[BB * HH * LL];  // SSM/gelu output, TRANSPOSED [seq][l]
__device__ float g_ar[HH * NN];
__device__ float g_ai[HH * NN];
__device__ float g_wr[HH * NN];
__device__ float g_win[HH * NN];
__device__ float g_apr[HH * NN];      // Re(dA^CLEN)
__device__ float g_api[HH * NN];      // Im(dA^CLEN)
__device__ float g_esr[BB * HH * CH * NN];
__device__ float g_esi[BB * HH * CH * NN];

// ------------------------------------------------------------------
// f32x2 packed math (Blackwell)
// ------------------------------------------------------------------
__device__ __forceinline__ ull pk2(float lo, float hi) {
    ull r;
    asm("mov.b64 %0, {%1, %2};" : "=l"(r) : "f"(lo), "f"(hi));
    return r;
}
__device__ __forceinline__ void upk2(ull v, float& lo, float& hi) {
    asm("mov.b64 {%0, %1}, %2;" : "=f"(lo), "=f"(hi) : "l"(v));
}
__device__ __forceinline__ ull fma2(ull a, ull b, ull c) {
    ull d;
    asm("fma.rn.f32x2 %0, %1, %2, %3;" : "=l"(d) : "l"(a), "l"(b), "l"(c));
    return d;
}
__device__ __forceinline__ ull mul2(ull a, ull b) {
    ull d;
    asm("mul.rn.f32x2 %0, %1, %2;" : "=l"(d) : "l"(a), "l"(b));
    return d;
}
__device__ __forceinline__ ull add2(ull a, ull b) {
    ull d;
    asm("add.rn.f32x2 %0, %1, %2;" : "=l"(d) : "l"(a), "l"(b));
    return d;
}

__device__ __forceinline__ float gelu1(float x) {
    const float c0 = 0.7978845608028654f;
    const float c1 = 0.044715f;
    float t = tanhf(c0 * (x + c1 * x * x * x));
    return 0.5f * x * (1.0f + t);
}

__device__ __forceinline__ uint32_t f2tf32(float x) {
    uint32_t r;
    asm("cvt.rna.tf32.f32 %0, %1;" : "=r"(r) : "f"(x));
    return r;
}

// mma.sync tf32 m16n8k8 (sm_80+, valid on target sm_103)
__device__ __forceinline__ void mma_tf32(float c[4],
                                         uint32_t a0, uint32_t a1,
                                         uint32_t a2, uint32_t a3,
                                         uint32_t b0, uint32_t b1) {
    asm volatile(
        "mma.sync.aligned.m16n8k8.row.col.f32.tf32.tf32.f32 "
        "{%0,%1,%2,%3}, {%4,%5,%6,%7}, {%8,%9}, {%0,%1,%2,%3};"
        : "+f"(c[0]), "+f"(c[1]), "+f"(c[2]), "+f"(c[3])
        : "r"(a0), "r"(a1), "r"(a2), "r"(a3), "r"(b0), "r"(b1));
}

// ------------------------------------------------------------------
// Encoder
// ------------------------------------------------------------------
__global__ void enc_kernel(const float* __restrict__ x,
                           const float* __restrict__ ew,
                           const float* __restrict__ eb) {
    __shared__ float sw[IND * HH];
    __shared__ float sx[16 * IND];
    int tid = threadIdx.x;
    for (int idx = tid; idx < HH * IND; idx += 256) {
        int h = idx / IND, i = idx % IND;
        sw[i * HH + h] = ew[idx];
    }
    int m0 = blockIdx.x * 16;
    for (int idx = tid; idx < 16 * IND; idx += 256)
        sx[idx] = x[(size_t)m0 * IND + idx];
    __syncthreads();
    float bias = eb[tid];
    for (int r = 0; r < 16; ++r) {
        float acc = bias;
        #pragma unroll
        for (int i = 0; i < IND; ++i)
            acc = fmaf(sx[r * IND + i], sw[i * HH + tid], acc);
        g_h[(size_t)(m0 + r) * HH + tid] = acc;
    }
}

// ------------------------------------------------------------------
// LayerNorm + transpose
// ------------------------------------------------------------------
__global__ void ln_kernel(const float* __restrict__ sc,
                          const float* __restrict__ bi) {
    __shared__ float sm[32][257];
    int tid  = threadIdx.x;
    int warp = tid >> 5;
    int lane = tid & 31;
    int m0 = blockIdx.x * 32;

    for (int r = warp; r < 32; r += 8) {
        const float* row = g_h + (size_t)(m0 + r) * HH;
        float4 v0 = *reinterpret_cast<const float4*>(row + lane * 4);
        float4 v1 = *reinterpret_cast<const float4*>(row + 128 + lane * 4);
        float s = v0.x + v0.y + v0.z + v0.w + v1.x + v1.y + v1.z + v1.w;
        float q = v0.x*v0.x + v0.y*v0.y + v0.z*v0.z + v0.w*v0.w
                + v1.x*v1.x + v1.y*v1.y + v1.z*v1.z + v1.w*v1.w;
        #pragma unroll
        for (int m = 16; m; m >>= 1) {
            s += __shfl_xor_sync(0xffffffffu, s, m);
            q += __shfl_xor_sync(0xffffffffu, q, m);
        }
        float mu  = s * (1.0f / 256.0f);
        float var = q * (1.0f / 256.0f) - mu * mu;
        float inv = rsqrtf(var + 1e-5f);
        int h0 = lane * 4, h1 = 128 + lane * 4;
        sm[r][h0+0] = (v0.x - mu) * inv * sc[h0+0] + bi[h0+0];
        sm[r][h0+1] = (v0.y - mu) * inv * sc[h0+1] + bi[h0+1];
        sm[r][h0+2] = (v0.z - mu) * inv * sc[h0+2] + bi[h0+2];
        sm[r][h0+3] = (v0.w - mu) * inv * sc[h0+3] + bi[h0+3];
        sm[r][h1+0] = (v1.x - mu) * inv * sc[h1+0] + bi[h1+0];
        sm[r][h1+1] = (v1.y - mu) * inv * sc[h1+1] + bi[h1+1];
        sm[r][h1+2] = (v1.z - mu) * inv * sc[h1+2] + bi[h1+2];
        sm[r][h1+3] = (v1.w - mu) * inv * sc[h1+3] + bi[h1+3];
    }
    __syncthreads();

    int b  = m0 >> 11;
    int l0 = m0 & 2047;
    for (int h = warp; h < HH; h += 8) {
        g_zt[((size_t)(b * HH + h)) * LL + l0 + lane] = sm[lane][h];
    }
}

// ------------------------------------------------------------------
// S4D discretization + dA^CLEN
// ------------------------------------------------------------------
__global__ void ssm_params_kernel(const float* __restrict__ lre,
                                  const float* __restrict__ lim,
                                  const float* __restrict__ cre,
                                  const float* __restrict__ cim,
                                  const float* __restrict__ lstep) {
    int idx = blockIdx.x * blockDim.x + threadIdx.x;
    if (idx >= HH * NN) return;
    int h = idx >> 6;
    float Lre = lre[idx], Lim = lim[idx];
    float Cre = cre[idx], Cim = cim[idx];
    float dt  = expf(lstep[h]);
    float mag = expf(Lre * dt);
    float th  = Lim * dt;
    float dar = mag * cosf(th);
    float dai = mag * sinf(th);
    float den = Lre * Lre + Lim * Lim;
    float nr = dar - 1.0f, ni = dai;
    float dbr = (nr * Lre + ni * Lim) / den;
    float dbi = (ni * Lre - nr * Lim) / den;
    float wr = Cre * dbr - Cim * dbi;
    float wi = Cre * dbi + Cim * dbr;
    g_ar[idx]  = dar;
    g_ai[idx]  = dai;
    g_wr[idx]  = 2.0f * wr;
    g_win[idx] = -2.0f * wi;
    double dtd = exp((double)lstep[h]);
    double mr  = exp((double)Lre * dtd * (double)CLEN);
    double thd = (double)Lim * dtd * (double)CLEN;
    g_apr[idx] = (float)(mr * cos(thd));
    g_api[idx] = (float)(mr * sin(thd));
}

// ------------------------------------------------------------------
// Scan pass 1: 8-step tiles + reduce-scatter, z prefetch,
// fused gelu for chunk 0.
// ------------------------------------------------------------------
__global__ void __launch_bounds__(256, 5) scan1_kernel(const float* __restrict__ dcoef) {
    int warp = (blockIdx.x * blockDim.x + threadIdx.x) >> 5;
    int lane = threadIdx.x & 31;
    int half = lane >> 4;
    int ln   = lane & 15;
    int unit = warp * 2 + half;
    int seq  = unit >> 2;
    int c    = unit & (CH - 1);
    int h = seq & 255;
    int base = h * NN + ln * 4;

    float a0r = g_ar[base+0], a1r = g_ar[base+1], a2r = g_ar[base+2], a3r = g_ar[base+3];
    float a0i = g_ai[base+0], a1i = g_ai[base+1], a2i = g_ai[base+2], a3i = g_ai[base+3];
    float w0r = g_wr[base+0], w1r = g_wr[base+1], w2r = g_wr[base+2], w3r = g_wr[base+3];
    float w0n = g_win[base+0], w1n = g_win[base+1], w2n = g_win[base+2], w3n = g_win[base+3];

    ull ar01 = pk2(a0r, a1r), ar23 = pk2(a2r, a3r);
    ull ai01 = pk2(a0i, a1i), ai23 = pk2(a2i, a3i);
    ull an01 = pk2(-a0i, -a1i), an23 = pk2(-a2i, -a3i);
    ull wr01 = pk2(w0r, w1r), wr23 = pk2(w2r, w3r);
    ull wn01 = pk2(w0n, w1n), wn23 = pk2(w2n, w3n);

    ull sr01 = 0ULL, si01 = 0ULL, sr23 = 0ULL, si23 = 0ULL;

    const float* zp = g_zt + (size_t)seq * LL + (size_t)c * CLEN;
    float*       yp = g_yt + (size_t)seq * LL + (size_t)c * CLEN;
    float dv = dcoef[h];
    bool first = (c == 0);
    int tstep = ln >> 1;
    bool wlane = ((ln & 1) == 0);

    float zv = zp[ln];
    for (int l0 = 0; l0 < CLEN; l0 += 16) {
        float zcur = zv;
        if (l0 + 16 < CLEN) zv = zp[l0 + 16 + ln];
        #pragma unroll
        for (int sub = 0; sub < 2; ++sub) {
            float c8[8];
            #pragma unroll
            for (int t = 0; t < 8; ++t) {
                float zb = __shfl_sync(0xffffffffu, zcur, sub * 8 + t, 16);
                ull z2 = pk2(zb, zb);
                ull t0 = fma2(an01, si01, z2);
                si01   = fma2(ai01, sr01, mul2(ar01, si01));
                sr01   = fma2(ar01, sr01, t0);
                ull t1 = fma2(an23, si23, z2);
                si23   = fma2(ai23, sr23, mul2(ar23, si23));
                sr23   = fma2(ar23, sr23, t1);
                ull av = fma2(wr01, sr01, mul2(wn01, si01));
                av = fma2(wr23, sr23, av);
                av = fma2(wn23, si23, av);
                float alo, ahi;
                upk2(av, alo, ahi);
                c8[t] = alo + ahi;
            }
            // reduce-scatter over 16 lanes: step t -> lane pair {2t, 2t+1}
            #pragma unroll
            for (int off = 8; off >= 2; off >>= 1) {
                int items = off >> 1;
                bool up = (ln & off) != 0;
                #pragma unroll
                for (int j = 0; j < items; ++j) {
                    float send = up ? c8[j] : c8[j + items];
                    float keep = up ? c8[j + items] : c8[j];
                    c8[j] = keep + __shfl_xor_sync(0xffffffffu, send, off, 16);
                }
            }
            c8[0] += __shfl_xor_sync(0xffffffffu, c8[0], 1, 16);
            float zz = __shfl_sync(0xffffffffu, zcur, sub * 8 + tstep, 16);
            float yv = fmaf(dv, zz, c8[0]);
            if (first) yv = gelu1(yv);
            if (wlane) yp[l0 + sub * 8 + tstep] = yv;
        }
    }

    float4 vr, vi;
    upk2(sr01, vr.x, vr.y); upk2(sr23, vr.z, vr.w);
    upk2(si01, vi.x, vi.y); upk2(si23, vi.z, vi.w);
    size_t so = (size_t)unit * NN + ln * 4;
    *reinterpret_cast<float4*>(&g_esr[so]) = vr;
    *reinterpret_cast<float4*>(&g_esi[so]) = vi;
}

// ------------------------------------------------------------------
// Scan pass 2: inline chunk-combine (Horner over chunk-end states),
// geometric correction, fused gelu. 8-step tiles.
// ------------------------------------------------------------------
__global__ void __launch_bounds__(256, 5) scan2_kernel() {
    int warp = (blockIdx.x * blockDim.x + threadIdx.x) >> 5;
    int lane = threadIdx.x & 31;
    int half = lane >> 4;
    int ln   = lane & 15;
    int unit = warp * 2 + half;
    int seq  = unit / (CH - 1);
    int c    = unit - seq * (CH - 1) + 1;   // 1..CH-1
    int h = seq & 255;
    int base = h * NN + ln * 4;

    float a0r = g_ar[base+0], a1r = g_ar[base+1], a2r = g_ar[base+2], a3r = g_ar[base+3];
    float a0i = g_ai[base+0], a1i = g_ai[base+1], a2i = g_ai[base+2], a3i = g_ai[base+3];
    float w0r = g_wr[base+0], w1r = g_wr[base+1], w2r = g_wr[base+2], w3r = g_wr[base+3];
    float w0n = g_win[base+0], w1n = g_win[base+1], w2n = g_win[base+2], w3n = g_win[base+3];

    // inline combine: S_init = sum_{j<c} P^{c-1-j} E_j  (Horner)
    float Sr[4] = {0.f, 0.f, 0.f, 0.f}, Si[4] = {0.f, 0.f, 0.f, 0.f};
    {
        float4 p_r = *reinterpret_cast<const float4*>(&g_apr[base]);
        float4 p_i = *reinterpret_cast<const float4*>(&g_api[base]);
        float pr[4] = {p_r.x, p_r.y, p_r.z, p_r.w};
        float pi[4] = {p_i.x, p_i.y, p_i.z, p_i.w};
        for (int j = 0; j < c; ++j) {
            size_t eo = (size_t)(seq * CH + j) * NN + ln * 4;
            float4 e_r = *reinterpret_cast<const float4*>(&g_esr[eo]);
            float4 e_i = *reinterpret_cast<const float4*>(&g_esi[eo]);
            float er[4] = {e_r.x, e_r.y, e_r.z, e_r.w};
            float ei[4] = {e_i.x, e_i.y, e_i.z, e_i.w};
            #pragma unroll
            for (int q = 0; q < 4; ++q) {
                float nsr = pr[q] * Sr[q] - pi[q] * Si[q] + er[q];
                float nsi = pr[q] * Si[q] + pi[q] * Sr[q] + ei[q];
                Sr[q] = nsr; Si[q] = nsi;
            }
        }
    }

    ull ar01 = pk2(a0r, a1r), ar23 = pk2(a2r, a3r);
    ull ai01 = pk2(a0i, a1i), ai23 = pk2(a2i, a3i);
    ull an01 = pk2(-a0i, -a1i), an23 = pk2(-a2i, -a3i);

    ull sr01 = pk2(Sr[0], Sr[1]), sr23 = pk2(Sr[2], Sr[3]);
    ull si01 = pk2(Si[0], Si[1]), si23 = pk2(Si[2], Si[3]);

    // t = dA * S_init
    ull tr01 = fma2(ar01, sr01, mul2(an01, si01));
    ull ti01 = fma2(ai01, sr01, mul2(ar01, si01));
    ull tr23 = fma2(ar23, sr23, mul2(an23, si23));
    ull ti23 = fma2(ai23, sr23, mul2(ar23, si23));

    // u = w2 .* t
    ull wr01 = pk2(w0r, w1r), wr23 = pk2(w2r, w3r);
    ull wn01 = pk2(w0n, w1n), wn23 = pk2(w2n, w3n);
    ull wm01 = pk2(-w0n, -w1n), wm23 = pk2(-w2n, -w3n);
    ull ur01 = fma2(wr01, tr01, mul2(wn01, ti01));
    ull ui01 = fma2(wr01, ti01, mul2(wm01, tr01));
    ull ur23 = fma2(wr23, tr23, mul2(wn23, ti23));
    ull ui23 = fma2(wr23, ti23, mul2(wm23, tr23));

    float* yp = g_yt + (size_t)seq * LL + (size_t)c * CLEN;
    int tstep = ln >> 1;
    bool wlane = ((ln & 1) == 0);

    float yv = yp[ln];
    for (int l0 = 0; l0 < CLEN; l0 += 16) {
        float ycur = yv;
        if (l0 + 16 < CLEN) yv = yp[l0 + 16 + ln];
        #pragma unroll
        for (int sub = 0; sub < 2; ++sub) {
            float c8[8];
            #pragma unroll
            for (int t = 0; t < 8; ++t) {
                ull sm = add2(ur01, ur23);
                float alo, ahi;
                upk2(sm, alo, ahi);
                c8[t] = alo + ahi;
                ull m0 = mul2(an01, ui01);
                ui01 = fma2(ai01, ur01, mul2(ar01, ui01));
                ur01 = fma2(ar01, ur01, m0);
                ull m1 = mul2(an23, ui23);
                ui23 = fma2(ai23, ur23, mul2(ar23, ui23));
                ur23 = fma2(ar23, ur23, m1);
            }
            #pragma unroll
            for (int off = 8; off >= 2; off >>= 1) {
                int items = off >> 1;
                bool up = (ln & off) != 0;
                #pragma unroll
                for (int j = 0; j < items; ++j) {
                    float send = up ? c8[j] : c8[j + items];
                    float keep = up ? c8[j + items] : c8[j];
                    c8[j] = keep + __shfl_xor_sync(0xffffffffu, send, off, 16);
                }
            }
            c8[0] += __shfl_xor_sync(0xffffffffu, c8[0], 1, 16);
            float yold = __shfl_sync(0xffffffffu, ycur, sub * 8 + tstep, 16);
            float ynew = gelu1(yold + c8[0]);
            if (wlane) yp[l0 + sub * 8 + tstep] = ynew;
        }
    }
}

// ------------------------------------------------------------------
// GLU GEMM via mma.sync tf32 (m16n8k8).
// ------------------------------------------------------------------
#define ASTR 136
#define BSTR 72
__global__ void __launch_bounds__(256) glu_gemm_mma(
        const float* __restrict__ W1, const float* __restrict__ W2,
        const float* __restrict__ b1, const float* __restrict__ b2) {
    __shared__ uint32_t As [32 * ASTR];   // [k][m], tf32
    __shared__ uint32_t Bs1[32 * BSTR];   // [k][n], tf32
    __shared__ uint32_t Bs2[32 * BSTR];

    int tid  = threadIdx.x;
    int wid  = tid >> 5;
    int lane = tid & 31;
    int g    = lane >> 2;
    int t    = lane & 3;
    int wm   = wid & 3;
    int wn   = wid >> 2;

    int m0  = blockIdx.x * 128;
    int n0  = blockIdx.y * 64;
    int bch = m0 >> 11;
    int ml0 = m0 & 2047;

    float acc1[2][4][4];
    float acc2[2][4][4];
    #pragma unroll
    for (int mi = 0; mi < 2; ++mi)
        #pragma unroll
        for (int nj = 0; nj < 4; ++nj)
            #pragma unroll
            for (int r = 0; r < 4; ++r) { acc1[mi][nj][r] = 0.f; acc2[mi][nj][r] = 0.f; }

    for (int kc = 0; kc < HH; kc += 32) {
        __syncthreads();
        #pragma unroll
        for (int it = 0; it < 4; ++it) {
            int item = it * 256 + tid;
            int krow = item >> 5;
            int c4   = (item & 31) * 4;
            const float* src = &g_yt[(size_t)(bch * HH + kc + krow) * LL + ml0 + c4];
            float4 v = *reinterpret_cast<const float4*>(src);
            uint32_t* dst = &As[krow * ASTR + c4];
            asm volatile("st.shared.v4.b32 [%0], {%1,%2,%3,%4};"
                :: "l"(dst), "r"(f2tf32(v.x)), "r"(f2tf32(v.y)),
                   "r"(f2tf32(v.z)), "r"(f2tf32(v.w)) : "memory");
        }
        #pragma unroll
        for (int it = 0; it < 2; ++it) {
            int item = it * 256 + tid;
            int gg = item & 63;
            int kq = item >> 6;
            size_t off = (size_t)(n0 + gg) * HH + kc + kq * 4;
            float4 w1 = *reinterpret_cast<const float4*>(&W1[off]);
            float4 w2 = *reinterpret_cast<const float4*>(&W2[off]);
            int kb = kq * 4;
            Bs1[(kb+0) * BSTR + gg] = f2tf32(w1.x);
            Bs1[(kb+1) * BSTR + gg] = f2tf32(w1.y);
            Bs1[(kb+2) * BSTR + gg] = f2tf32(w1.z);
            Bs1[(kb+3) * BSTR + gg] = f2tf32(w1.w);
            Bs2[(kb+0) * BSTR + gg] = f2tf32(w2.x);
            Bs2[(kb+1) * BSTR + gg] = f2tf32(w2.y);
            Bs2[(kb+2) * BSTR + gg] = f2tf32(w2.z);
            Bs2[(kb+3) * BSTR + gg] = f2tf32(w2.w);
        }
        __syncthreads();

        #pragma unroll
        for (int ks = 0; ks < 4; ++ks) {
            int kb = ks * 8;
            uint32_t af[2][4];
            #pragma unroll
            for (int mi = 0; mi < 2; ++mi) {
                int mrow = wm * 32 + mi * 16;
                af[mi][0] = As[(kb + t)     * ASTR + mrow + g];
                af[mi][1] = As[(kb + t)     * ASTR + mrow + g + 8];
                af[mi][2] = As[(kb + t + 4) * ASTR + mrow + g];
                af[mi][3] = As[(kb + t + 4) * ASTR + mrow + g + 8];
            }
            #pragma unroll
            for (int nj = 0; nj < 4; ++nj) {
                int ncol = wn * 32 + nj * 8 + g;
                uint32_t bA0 = Bs1[(kb + t)     * BSTR + ncol];
                uint32_t bA1 = Bs1[(kb + t + 4) * BSTR + ncol];
                uint32_t bB0 = Bs2[(kb + t)     * BSTR + ncol];
                uint32_t bB1 = Bs2[(kb + t + 4) * BSTR + ncol];
                #pragma unroll
                for (int mi = 0; mi < 2; ++mi) {
                    mma_tf32(acc1[mi][nj], af[mi][0], af[mi][1], af[mi][2], af[mi][3], bA0, bA1);
                    mma_tf32(acc2[mi][nj], af[mi][0], af[mi][1], af[mi][2], af[mi][3], bB0, bB1);
                }
            }
        }
    }

    #pragma unroll
    for (int nj = 0; nj < 4; ++nj) {
        int ncol = n0 + wn * 32 + nj * 8 + t * 2;
        float bb1a = b1[ncol], bb1b = b1[ncol + 1];
        float bb2a = b2[ncol], bb2b = b2[ncol + 1];
        #pragma unroll
        for (int mi = 0; mi < 2; ++mi) {
            #pragma unroll
            for (int rr = 0; rr < 2; ++rr) {
                int mrow = m0 + wm * 32 + mi * 16 + g + rr * 8;
                float* hp = &g_h[(size_t)mrow * HH + ncol];
                float2 hv = *reinterpret_cast<float2*>(hp);
                float d1a = acc1[mi][nj][rr * 2 + 0] + bb1a;
                float d1b = acc1[mi][nj][rr * 2 + 1] + bb1b;
                float d2a = acc2[mi][nj][rr * 2 + 0] + bb2a;
                float d2b = acc2[mi][nj][rr * 2 + 1] + bb2b;
                hv.x += d1a * (1.0f / (1.0f + expf(-d2a)));
                hv.y += d1b * (1.0f / (1.0f + expf(-d2b)));
                *reinterpret_cast<float2*>(hp) = hv;
            }
        }
    }
}

// ------------------------------------------------------------------
// Decoder
// ------------------------------------------------------------------
__global__ void dec_kernel(const float* __restrict__ dw,
                           const float* __restrict__ db,
                           float* __restrict__ out) {
    int warp = (blockIdx.x * blockDim.x + threadIdx.x) >> 5;
    int lane = threadIdx.x & 31;
    const float* row = g_h + (size_t)warp * HH;
    float hr[8];
    #pragma unroll
    for (int k = 0; k < 8; ++k) hr[k] = row[lane + 32 * k];
    for (int o = 0; o < OUTD; ++o) {
        const float* wrow = dw + o * HH + lane;
        float acc = 0.0f;
        #pragma unroll
        for (int k = 0; k < 8; ++k) acc = fmaf(hr[k], wrow[32 * k], acc);
        #pragma unroll
        for (int m = 16; m; m >>= 1) acc += __shfl_xor_sync(0xffffffffu, acc, m);
        if (lane == 0) out[(size_t)warp * OUTD + o] = acc + db[o];
    }
}

// ------------------------------------------------------------------
extern "C" void kernel_launch(void* const* d_in, const int* in_sizes, int n_in,
                              void* d_out, int out_size) {
    const float* x     = (const float*)d_in[0];
    const float* enc_w = (const float*)d_in[1];
    const float* enc_b = (const float*)d_in[2];
    const float* lre   = (const float*)d_in[3];
    const float* lim   = (const float*)d_in[4];
    const float* cre   = (const float*)d_in[5];
    const float* cim   = (const float*)d_in[6];
    const float* dd    = (const float*)d_in[7];
    const float* lstep = (const float*)d_in[8];
    const float* lns   = (const float*)d_in[9];
    const float* lnb   = (const float*)d_in[10];
    const float* ow    = (const float*)d_in[11];
    const float* ob    = (const float*)d_in[12];
    const float* o2w   = (const float*)d_in[13];
    const float* o2b   = (const float*)d_in[14];
    const float* dw    = (const float*)d_in[15];
    const float* db    = (const float*)d_in[16];
    float* out = (float*)d_out;

    enc_kernel<<<(BB * LL) / 16, 256>>>(x, enc_w, enc_b);

    for (int li = 0; li < NLAY; ++li) {
        ln_kernel<<<(BB * LL) / 32, 256>>>(lns + li * HH, lnb + li * HH);
        ssm_params_kernel<<<(HH * NN) / 256, 256>>>(
            lre + li * HH * NN, lim + li * HH * NN,
            cre + li * HH * NN, cim + li * HH * NN, lstep + li * HH);
        scan1_kernel<<<(BB * HH * CH) / 16, 256>>>(dd + li * HH);
        scan2_kernel<<<(BB * HH * (CH - 1)) / 16, 256>>>();
        glu_gemm_mma<<<dim3((BB * LL) / 128, HH / 64), 256>>>(
            ow + li * HH * HH, o2w + li * HH * HH,
            ob + li * HH, o2b + li * HH);
    }

    dec_kernel<<<(BB * LL) / 8, 256>>>(dw, db, out);
}